// round 3
// baseline (speedup 1.0000x reference)
#include <cuda_runtime.h>
#include <math.h>

#define BSZ   8192
#define NBLK  8
#define HDIM  256
#define DDIM  256
#define DKIN  16
#define DVIN  32
#define NHC   4
#define DKC   8
#define KACT  4

// ---------------- device scratch (static, no allocation) ----------------
__device__ float g_mask  [BSZ * NBLK];                 // (B,N)
__device__ float g_inputs[BSZ * NBLK * DVIN];          // (B,N,32), mask applied
__device__ float g_hsnew [BSZ * NBLK * HDIM];          // (B,N,256)
__device__ float g_q2    [BSZ * NBLK * 32];            // (B,N,32)
__device__ float g_k2    [BSZ * NBLK * 32];            // (B,N,32)
__device__ float g_att   [BSZ * NHC * NBLK * NBLK];    // (B,4,8,8)
__device__ float g_v2    [BSZ * NBLK * 1024];          // (B,m,1024)
__device__ float g_ctx   [BSZ * NBLK * 1024];          // (B,n,1024)

// ================= Kernel 1: gating attention, mask, inputs ==============
// one warp per batch element; block = 8 warps
__global__ __launch_bounds__(256) void k1_gating(
    const float* __restrict__ x1, const float* __restrict__ x2,
    const float* __restrict__ hs,
    const float* __restrict__ Wkey, const float* __restrict__ bkey,
    const float* __restrict__ Wval, const float* __restrict__ bval,
    const float* __restrict__ Wq)
{
    const int w    = threadIdx.x >> 5;
    const int lane = threadIdx.x & 31;
    const int b    = blockIdx.x * 8 + w;

    __shared__ float sKL[8][48];
    __shared__ float sVL[8][96];
    __shared__ float sQL[8][128];
    __shared__ float sS [8][24];
    __shared__ float sM [8][8];

    // kL[s][j] = bkey[j] + x_s . Wkey[:,j]   (x_2 == 0)
    for (int o = lane; o < 48; o += 32) {
        int s = o >> 4, j = o & 15;
        float acc = bkey[j];
        if (s < 2) {
            const float* xp = s ? (x2 + b * DDIM) : (x1 + b * DDIM);
            #pragma unroll 8
            for (int d = 0; d < DDIM; d++) acc += xp[d] * Wkey[d * DKIN + j];
        }
        sKL[w][o] = acc;
    }
    // vL[s][j]
    for (int o = lane; o < 96; o += 32) {
        int s = o >> 5, j = o & 31;
        float acc = bval[j];
        if (s < 2) {
            const float* xp = s ? (x2 + b * DDIM) : (x1 + b * DDIM);
            #pragma unroll 8
            for (int d = 0; d < DDIM; d++) acc += xp[d] * Wval[d * DVIN + j];
        }
        sVL[w][o] = acc;
    }
    // qL[n][j] = hs[b,n,:] . Wq[n,:,j]
    for (int o = lane; o < 128; o += 32) {
        int nn = o >> 4, j = o & 15;
        const float* hp = hs + (b * NBLK + nn) * HDIM;
        const float* wp = Wq + nn * HDIM * DKIN + j;
        float acc = 0.f;
        #pragma unroll 8
        for (int d = 0; d < DDIM; d++) acc += hp[d] * wp[d * DKIN];
        sQL[w][o] = acc;
    }
    __syncwarp();

    // scores[n][s] = 0.25 * qL[n].kL[s]
    for (int o = lane; o < 24; o += 32) {
        int nn = o / 3, s = o % 3;
        float acc = 0.f;
        #pragma unroll
        for (int j = 0; j < 16; j++) acc += sQL[w][nn * 16 + j] * sKL[w][s * 16 + j];
        sS[w][o] = acc * 0.25f;
    }
    __syncwarp();

    // mask: top (N-KACT) null scores are blocked (ties -> lower index wins, as lax.top_k)
    if (lane < 8) {
        float nu = sS[w][lane * 3 + 2];
        int rank = 0;
        #pragma unroll
        for (int n2 = 0; n2 < 8; n2++) {
            float nu2 = sS[w][n2 * 3 + 2];
            rank += (nu2 > nu) || (nu2 == nu && n2 < lane);
        }
        float m = (rank < (NBLK - KACT)) ? 0.f : 1.f;
        sM[w][lane] = m;
        g_mask[b * NBLK + lane] = m;
    }
    __syncwarp();

    // probs (softmax over 3) then inputs = mask * probs . vL
    for (int o = lane; o < 256; o += 32) {
        int nn = o >> 5, j = o & 31;
        float s0 = sS[w][nn * 3 + 0];
        float s1 = sS[w][nn * 3 + 1];
        float s2 = sS[w][nn * 3 + 2];
        float mx = fmaxf(s0, fmaxf(s1, s2));
        float e0 = expf(s0 - mx), e1 = expf(s1 - mx), e2 = expf(s2 - mx);
        float inv = 1.f / (e0 + e1 + e2);
        float val = (e0 * sVL[w][j] + e1 * sVL[w][32 + j] + e2 * sVL[w][64 + j])
                    * inv * sM[w][nn];
        g_inputs[(b * NBLK + nn) * DVIN + j] = val;
    }
}

// ================= Kernel 2: fused GRU (gate_x + gate_h GEMM + epilogue) ==
// grid (128 btiles, 8 htiles, 8 n), 256 threads; tile: 64 rows x 32 h-cols
// each thread: 4 rows x (3 gate groups x 2 h) accumulators for gx and gh
__global__ __launch_bounds__(256) void k2_gru(
    const float* __restrict__ hs,
    const float* __restrict__ Wx2h,
    const float* __restrict__ Wh2h)
{
    const int n  = blockIdx.z;
    const int b0 = blockIdx.x * 64;
    const int h0 = blockIdx.y * 32;
    const int tid = threadIdx.x;
    const int tx = tid & 15, ty = tid >> 4;

    __shared__ float sA[64][33];
    __shared__ float sW[32][96];

    float gx[4][3][2], gh[4][3][2];
    #pragma unroll
    for (int i = 0; i < 4; i++)
        #pragma unroll
        for (int g = 0; g < 3; g++) { gx[i][g][0]=gx[i][g][1]=0.f; gh[i][g][0]=gh[i][g][1]=0.f; }

    // ---- gate_x: K = 32 (inputs already mask-scaled) ----
    for (int l = tid; l < 64 * 32; l += 256) {
        int row = l >> 5, k = l & 31;
        sA[row][k] = g_inputs[((b0 + row) * NBLK + n) * DVIN + k];
    }
    for (int l = tid; l < 32 * 96; l += 256) {
        int k = l / 96, c = l % 96;
        int g = c >> 5, hh = c & 31;
        sW[k][c] = Wx2h[(n * 32 + k) * 768 + g * 256 + h0 + hh];
    }
    __syncthreads();
    #pragma unroll
    for (int k = 0; k < 32; k++) {
        float a0 = sA[ty][k], a1 = sA[ty + 16][k], a2 = sA[ty + 32][k], a3 = sA[ty + 48][k];
        #pragma unroll
        for (int g = 0; g < 3; g++) {
            float2 wv = *(const float2*)&sW[k][g * 32 + 2 * tx];
            gx[0][g][0] += a0 * wv.x; gx[0][g][1] += a0 * wv.y;
            gx[1][g][0] += a1 * wv.x; gx[1][g][1] += a1 * wv.y;
            gx[2][g][0] += a2 * wv.x; gx[2][g][1] += a2 * wv.y;
            gx[3][g][0] += a3 * wv.x; gx[3][g][1] += a3 * wv.y;
        }
    }
    __syncthreads();

    // ---- gate_h: K = 256 ----
    for (int kt = 0; kt < 256; kt += 32) {
        for (int l = tid; l < 64 * 32; l += 256) {
            int row = l >> 5, k = l & 31;
            sA[row][k] = hs[((b0 + row) * NBLK + n) * HDIM + kt + k];
        }
        for (int l = tid; l < 32 * 96; l += 256) {
            int k = l / 96, c = l % 96;
            int g = c >> 5, hh = c & 31;
            sW[k][c] = Wh2h[(n * 256 + kt + k) * 768 + g * 256 + h0 + hh];
        }
        __syncthreads();
        #pragma unroll
        for (int k = 0; k < 32; k++) {
            float a0 = sA[ty][k], a1 = sA[ty + 16][k], a2 = sA[ty + 32][k], a3 = sA[ty + 48][k];
            #pragma unroll
            for (int g = 0; g < 3; g++) {
                float2 wv = *(const float2*)&sW[k][g * 32 + 2 * tx];
                gh[0][g][0] += a0 * wv.x; gh[0][g][1] += a0 * wv.y;
                gh[1][g][0] += a1 * wv.x; gh[1][g][1] += a1 * wv.y;
                gh[2][g][0] += a2 * wv.x; gh[2][g][1] += a2 * wv.y;
                gh[3][g][0] += a3 * wv.x; gh[3][g][1] += a3 * wv.y;
            }
        }
        __syncthreads();
    }

    // ---- epilogue: GRU update ----
    #pragma unroll
    for (int i = 0; i < 4; i++) {
        int b = b0 + ty + 16 * i;
        #pragma unroll
        for (int p = 0; p < 2; p++) {
            int h = h0 + 2 * tx + p;
            float r  = 1.f / (1.f + expf(-(gx[i][0][p] + gh[i][0][p])));
            float z  = 1.f / (1.f + expf(-(gx[i][1][p] + gh[i][1][p])));
            float nv = tanhf(gx[i][2][p] + r * gh[i][2][p]);
            int idx = (b * NBLK + n) * HDIM + h;
            float hold = hs[idx];
            g_hsnew[idx] = nv + z * (hold - nv);
        }
    }
}

// ================= Kernel 3a1: q2/k2 projection GEMM ======================
// grid (128, 1, 8); tile 64 rows x 64 cols (cols 0..31 -> Wq_, 32..63 -> Wk_)
__global__ __launch_bounds__(256) void k3a1_qk(
    const float* __restrict__ Wq_, const float* __restrict__ Wk_)
{
    const int n  = blockIdx.z;
    const int b0 = blockIdx.x * 64;
    const int tid = threadIdx.x;
    const int tx = tid & 15, ty = tid >> 4;

    __shared__ float sA[64][33];
    __shared__ float sW[32][64];

    float acc[4][4] = {};
    for (int kt = 0; kt < 256; kt += 32) {
        for (int l = tid; l < 64 * 32; l += 256) {
            int row = l >> 5, k = l & 31;
            sA[row][k] = g_hsnew[((b0 + row) * NBLK + n) * HDIM + kt + k];
        }
        for (int l = tid; l < 32 * 64; l += 256) {
            int k = l >> 6, c = l & 63;
            sW[k][c] = (c < 32) ? Wq_[(n * 256 + kt + k) * 32 + c]
                                : Wk_[(n * 256 + kt + k) * 32 + (c - 32)];
        }
        __syncthreads();
        #pragma unroll
        for (int k = 0; k < 32; k++) {
            float a0 = sA[ty][k], a1 = sA[ty + 16][k], a2 = sA[ty + 32][k], a3 = sA[ty + 48][k];
            float4 wv = *(const float4*)&sW[k][tx * 4];
            acc[0][0]+=a0*wv.x; acc[0][1]+=a0*wv.y; acc[0][2]+=a0*wv.z; acc[0][3]+=a0*wv.w;
            acc[1][0]+=a1*wv.x; acc[1][1]+=a1*wv.y; acc[1][2]+=a1*wv.z; acc[1][3]+=a1*wv.w;
            acc[2][0]+=a2*wv.x; acc[2][1]+=a2*wv.y; acc[2][2]+=a2*wv.z; acc[2][3]+=a2*wv.w;
            acc[3][0]+=a3*wv.x; acc[3][1]+=a3*wv.y; acc[3][2]+=a3*wv.z; acc[3][3]+=a3*wv.w;
        }
        __syncthreads();
    }
    #pragma unroll
    for (int i = 0; i < 4; i++) {
        int b = b0 + ty + 16 * i;
        float4 v = make_float4(acc[i][0], acc[i][1], acc[i][2], acc[i][3]);
        if (tx < 8) *(float4*)&g_q2[(b * NBLK + n) * 32 + tx * 4] = v;
        else        *(float4*)&g_k2[(b * NBLK + n) * 32 + (tx - 8) * 4] = v;
    }
}

// ================= Kernel 3a2: 4-head 8x8 attention + softmax + mask ======
__global__ __launch_bounds__(256) void k3a2_att()
{
    const int w = threadIdx.x >> 5, lane = threadIdx.x & 31;
    const int b = blockIdx.x * 8 + w;

    __shared__ float sQ[8][256];
    __shared__ float sK[8][256];
    for (int l = lane; l < 256; l += 32) {
        sQ[w][l] = g_q2[b * 256 + l];
        sK[w][l] = g_k2[b * 256 + l];
    }
    __syncwarp();

    const int h = lane >> 3, nq = lane & 7;   // 32 (h, n) pairs, one per lane
    float sc[8], mx = -1e30f;
    #pragma unroll
    for (int m = 0; m < 8; m++) {
        float s = 0.f;
        #pragma unroll
        for (int dk = 0; dk < 8; dk++)
            s += sQ[w][nq * 32 + h * 8 + dk] * sK[w][m * 32 + h * 8 + dk];
        s *= 0.35355339059327373f;   // DK_C^-0.5
        sc[m] = s;
        mx = fmaxf(mx, s);
    }
    float den = 0.f;
    #pragma unroll
    for (int m = 0; m < 8; m++) { sc[m] = expf(sc[m] - mx); den += sc[m]; }
    float scale = g_mask[b * NBLK + nq] / den;
    #pragma unroll
    for (int m = 0; m < 8; m++)
        g_att[((b * NHC + h) * NBLK + nq) * NBLK + m] = sc[m] * scale;
}

// ================= Kernel 3b: v2 = hs_new @ Wv_ ===========================
// grid (128, 16, 8); tile 64 x 64, K=256
__global__ __launch_bounds__(256) void k3b_v2(const float* __restrict__ Wv_)
{
    const int n  = blockIdx.z;
    const int b0 = blockIdx.x * 64;
    const int o0 = blockIdx.y * 64;
    const int tid = threadIdx.x;
    const int tx = tid & 15, ty = tid >> 4;

    __shared__ float sA[64][33];
    __shared__ float sW[32][64];

    float acc[4][4] = {};
    for (int kt = 0; kt < 256; kt += 32) {
        for (int l = tid; l < 64 * 32; l += 256) {
            int row = l >> 5, k = l & 31;
            sA[row][k] = g_hsnew[((b0 + row) * NBLK + n) * HDIM + kt + k];
        }
        for (int l = tid; l < 32 * 64; l += 256) {
            int k = l >> 6, c = l & 63;
            sW[k][c] = Wv_[(n * 256 + kt + k) * 1024 + o0 + c];
        }
        __syncthreads();
        #pragma unroll
        for (int k = 0; k < 32; k++) {
            float a0 = sA[ty][k], a1 = sA[ty + 16][k], a2 = sA[ty + 32][k], a3 = sA[ty + 48][k];
            float4 wv = *(const float4*)&sW[k][tx * 4];
            acc[0][0]+=a0*wv.x; acc[0][1]+=a0*wv.y; acc[0][2]+=a0*wv.z; acc[0][3]+=a0*wv.w;
            acc[1][0]+=a1*wv.x; acc[1][1]+=a1*wv.y; acc[1][2]+=a1*wv.z; acc[1][3]+=a1*wv.w;
            acc[2][0]+=a2*wv.x; acc[2][1]+=a2*wv.y; acc[2][2]+=a2*wv.z; acc[2][3]+=a2*wv.w;
            acc[3][0]+=a3*wv.x; acc[3][1]+=a3*wv.y; acc[3][2]+=a3*wv.z; acc[3][3]+=a3*wv.w;
        }
        __syncthreads();
    }
    #pragma unroll
    for (int i = 0; i < 4; i++) {
        int b = b0 + ty + 16 * i;
        float4 v = make_float4(acc[i][0], acc[i][1], acc[i][2], acc[i][3]);
        *(float4*)&g_v2[(b * NBLK + n) * 1024 + o0 + tx * 4] = v;
    }
}

// ================= Kernel 3c: ctx = att @ v2 (per-b, smem resident) =======
__global__ __launch_bounds__(256) void k3c_ctx()
{
    const int b = blockIdx.x;
    __shared__ float sV[8 * 1024];
    __shared__ float sAtt[256];

    const float* vb = g_v2 + b * 8192;
    for (int l = threadIdx.x; l < 8192; l += 256) sV[l] = vb[l];
    sAtt[threadIdx.x] = g_att[b * 256 + threadIdx.x];
    __syncthreads();

    float* cb = g_ctx + b * 8192;
    for (int l = threadIdx.x; l < 8192; l += 256) {
        int nq = l >> 10, c = l & 1023, g = c >> 8;
        const float* ap = &sAtt[(g * 8 + nq) * 8];
        float acc = 0.f;
        #pragma unroll
        for (int m = 0; m < 8; m++) acc += ap[m] * sV[m * 1024 + c];
        cb[l] = acc;
    }
}

// ================= Kernel 3d: out = ctx @ Wout + hs_new, masked mix ======
// grid (128, 4, 8); tile 64 x 64, K=1024
__global__ __launch_bounds__(256) void k3d_out(
    const float* __restrict__ Wout, const float* __restrict__ hs,
    float* __restrict__ out)
{
    const int n  = blockIdx.z;
    const int b0 = blockIdx.x * 64;
    const int o0 = blockIdx.y * 64;
    const int tid = threadIdx.x;
    const int tx = tid & 15, ty = tid >> 4;

    __shared__ float sA[64][33];
    __shared__ float sW[32][64];

    float acc[4][4] = {};
    for (int kt = 0; kt < 1024; kt += 32) {
        for (int l = tid; l < 64 * 32; l += 256) {
            int row = l >> 5, k = l & 31;
            sA[row][k] = g_ctx[((b0 + row) * NBLK + n) * 1024 + kt + k];
        }
        for (int l = tid; l < 32 * 64; l += 256) {
            int k = l >> 6, c = l & 63;
            sW[k][c] = Wout[(n * 1024 + kt + k) * 256 + o0 + c];
        }
        __syncthreads();
        #pragma unroll
        for (int k = 0; k < 32; k++) {
            float a0 = sA[ty][k], a1 = sA[ty + 16][k], a2 = sA[ty + 32][k], a3 = sA[ty + 48][k];
            float4 wv = *(const float4*)&sW[k][tx * 4];
            acc[0][0]+=a0*wv.x; acc[0][1]+=a0*wv.y; acc[0][2]+=a0*wv.z; acc[0][3]+=a0*wv.w;
            acc[1][0]+=a1*wv.x; acc[1][1]+=a1*wv.y; acc[1][2]+=a1*wv.z; acc[1][3]+=a1*wv.w;
            acc[2][0]+=a2*wv.x; acc[2][1]+=a2*wv.y; acc[2][2]+=a2*wv.z; acc[2][3]+=a2*wv.w;
            acc[3][0]+=a3*wv.x; acc[3][1]+=a3*wv.y; acc[3][2]+=a3*wv.z; acc[3][3]+=a3*wv.w;
        }
        __syncthreads();
    }
    #pragma unroll
    for (int i = 0; i < 4; i++) {
        int b = b0 + ty + 16 * i;
        float m = g_mask[b * NBLK + n];
        int idx = (b * NBLK + n) * HDIM + o0 + tx * 4;
        float4 hn = *(const float4*)&g_hsnew[idx];
        float4 ho = *(const float4*)&hs[idx];
        float4 r;
        r.x = m * (acc[i][0] + hn.x) + (1.f - m) * ho.x;
        r.y = m * (acc[i][1] + hn.y) + (1.f - m) * ho.y;
        r.z = m * (acc[i][2] + hn.z) + (1.f - m) * ho.z;
        r.w = m * (acc[i][3] + hn.w) + (1.f - m) * ho.w;
        *(float4*)&out[idx] = r;
    }
}

// =========================== launch ======================================
extern "C" void kernel_launch(void* const* d_in, const int* in_sizes, int n_in,
                              void* d_out, int out_size)
{
    const float* x1   = (const float*)d_in[0];
    const float* x2   = (const float*)d_in[1];
    const float* hs   = (const float*)d_in[2];
    const float* Wkey = (const float*)d_in[3];
    const float* bkey = (const float*)d_in[4];
    const float* Wval = (const float*)d_in[5];
    const float* bval = (const float*)d_in[6];
    const float* Wq   = (const float*)d_in[7];
    const float* Wq_  = (const float*)d_in[8];
    const float* Wk_  = (const float*)d_in[9];
    const float* Wv_  = (const float*)d_in[10];
    const float* Wout = (const float*)d_in[11];
    const float* Wx2h = (const float*)d_in[12];
    const float* Wh2h = (const float*)d_in[13];
    float* out = (float*)d_out;

    k1_gating<<<BSZ / 8, 256>>>(x1, x2, hs, Wkey, bkey, Wval, bval, Wq);
    k2_gru   <<<dim3(BSZ / 64, HDIM / 32, NBLK), 256>>>(hs, Wx2h, Wh2h);
    k3a1_qk  <<<dim3(BSZ / 64, 1, NBLK), 256>>>(Wq_, Wk_);
    k3a2_att <<<BSZ / 8, 256>>>();
    k3b_v2   <<<dim3(BSZ / 64, 16, NBLK), 256>>>(Wv_);
    k3c_ctx  <<<BSZ, 256>>>();
    k3d_out  <<<dim3(BSZ / 64, 4, NBLK), 256>>>(Wout, hs, out);
}

// round 5
// speedup vs baseline: 1.8058x; 1.8058x over previous
#include <cuda_runtime.h>
#include <math.h>
#include <stdint.h>

#define BSZ   8192
#define NBLK  8
#define HDIM  256
#define DDIM  256
#define DKIN  16
#define DVIN  32
#define NHC   4
#define KACT  4

// ---------------- device scratch ----------------
__device__ float g_mask  [BSZ * NBLK];
__device__ float g_inputs[BSZ * NBLK * DVIN];
__device__ float g_hsnew [BSZ * NBLK * HDIM];
__device__ float g_q2    [BSZ * NBLK * 32];
__device__ float g_k2    [BSZ * NBLK * 32];
__device__ float g_att   [BSZ * NHC * NBLK * NBLK];
__device__ float g_v2    [BSZ * NBLK * 1024];
__device__ float g_ctx   [BSZ * NBLK * 1024];

// ---------------- mma helpers (arch-agnostic PTX, sm_80+) ----------------
__device__ __forceinline__ uint32_t f2tf(float f) {
    uint32_t u;
    asm("cvt.rna.tf32.f32 %0, %1;" : "=r"(u) : "f"(f));
    return u;
}
__device__ __forceinline__ void mma8(float* d, uint32_t a0, uint32_t a1, uint32_t a2,
                                     uint32_t a3, uint32_t b0, uint32_t b1) {
    asm volatile("mma.sync.aligned.m16n8k8.row.col.f32.tf32.tf32.f32 "
        "{%0,%1,%2,%3}, {%4,%5,%6,%7}, {%8,%9}, {%0,%1,%2,%3};"
        : "+f"(d[0]), "+f"(d[1]), "+f"(d[2]), "+f"(d[3])
        : "r"(a0), "r"(a1), "r"(a2), "r"(a3), "r"(b0), "r"(b1));
}
__device__ __forceinline__ float sigf(float x) { return 1.f / (1.f + expf(-x)); }

// ================= Kernel 1: gating attention, mask, inputs (SIMT) =======
__global__ __launch_bounds__(256) void k1_gating(
    const float* __restrict__ x1, const float* __restrict__ x2,
    const float* __restrict__ hs,
    const float* __restrict__ Wkey, const float* __restrict__ bkey,
    const float* __restrict__ Wval, const float* __restrict__ bval,
    const float* __restrict__ Wq)
{
    const int w    = threadIdx.x >> 5;
    const int lane = threadIdx.x & 31;
    const int b    = blockIdx.x * 8 + w;

    __shared__ float sKL[8][48];
    __shared__ float sVL[8][96];
    __shared__ float sQL[8][128];
    __shared__ float sS [8][24];
    __shared__ float sM [8][8];

    for (int o = lane; o < 48; o += 32) {
        int s = o >> 4, j = o & 15;
        float acc = bkey[j];
        if (s < 2) {
            const float* xp = s ? (x2 + b * DDIM) : (x1 + b * DDIM);
            #pragma unroll 8
            for (int d = 0; d < DDIM; d++) acc += xp[d] * Wkey[d * DKIN + j];
        }
        sKL[w][o] = acc;
    }
    for (int o = lane; o < 96; o += 32) {
        int s = o >> 5, j = o & 31;
        float acc = bval[j];
        if (s < 2) {
            const float* xp = s ? (x2 + b * DDIM) : (x1 + b * DDIM);
            #pragma unroll 8
            for (int d = 0; d < DDIM; d++) acc += xp[d] * Wval[d * DVIN + j];
        }
        sVL[w][o] = acc;
    }
    for (int o = lane; o < 128; o += 32) {
        int nn = o >> 4, j = o & 15;
        const float* hp = hs + (b * NBLK + nn) * HDIM;
        const float* wp = Wq + nn * HDIM * DKIN + j;
        float acc = 0.f;
        #pragma unroll 8
        for (int d = 0; d < DDIM; d++) acc += hp[d] * wp[d * DKIN];
        sQL[w][o] = acc;
    }
    __syncwarp();

    for (int o = lane; o < 24; o += 32) {
        int nn = o / 3, s = o % 3;
        float acc = 0.f;
        #pragma unroll
        for (int j = 0; j < 16; j++) acc += sQL[w][nn * 16 + j] * sKL[w][s * 16 + j];
        sS[w][o] = acc * 0.25f;
    }
    __syncwarp();

    if (lane < 8) {
        float nu = sS[w][lane * 3 + 2];
        int rank = 0;
        #pragma unroll
        for (int n2 = 0; n2 < 8; n2++) {
            float nu2 = sS[w][n2 * 3 + 2];
            rank += (nu2 > nu) || (nu2 == nu && n2 < lane);
        }
        float m = (rank < (NBLK - KACT)) ? 0.f : 1.f;
        sM[w][lane] = m;
        g_mask[b * NBLK + lane] = m;
    }
    __syncwarp();

    for (int o = lane; o < 256; o += 32) {
        int nn = o >> 5, j = o & 31;
        float s0 = sS[w][nn * 3 + 0], s1 = sS[w][nn * 3 + 1], s2 = sS[w][nn * 3 + 2];
        float mx = fmaxf(s0, fmaxf(s1, s2));
        float e0 = expf(s0 - mx), e1 = expf(s1 - mx), e2 = expf(s2 - mx);
        float inv = 1.f / (e0 + e1 + e2);
        float val = (e0 * sVL[w][j] + e1 * sVL[w][32 + j] + e2 * sVL[w][64 + j])
                    * inv * sM[w][nn];
        g_inputs[(b * NBLK + nn) * DVIN + j] = val;
    }
}

// ================= Kernel 2: fused GRU via tf32 mma =======================
// grid (128, 8, 8): tile 64 rows x 32 h (x3 gates = 96 B-cols). 8 warps:
// wm=warp>>1 (16 rows each), wn=warp&1 (16 h-cols, all 3 gates).
__global__ __launch_bounds__(256) void k2_gru(
    const float* __restrict__ hs,
    const float* __restrict__ Wx2h,
    const float* __restrict__ Wh2h)
{
    const int n  = blockIdx.z;
    const int b0 = blockIdx.x * 64;
    const int h0 = blockIdx.y * 32;
    const int tid = threadIdx.x, warp = tid >> 5, lane = tid & 31;
    const int wm = warp >> 1, wn = warp & 1;
    const int lr = lane >> 2, lc = lane & 3;

    __shared__ uint32_t sA[64 * 36];   // [row][k] tf32
    __shared__ uint32_t sB[96 * 36];   // [col][k] tf32 (col = g*32 + h)

    float gx[2][3][4] = {}, gh[2][3][4] = {};

    // ---- phase 1: gate_x (K = 32, A = g_inputs, B = Wx2h) ----
    for (int l = tid; l < 512; l += 256) {             // 64 rows x 8 float4
        int r = l >> 3, k4 = l & 7;
        float4 v = *(const float4*)&g_inputs[((b0 + r) * NBLK + n) * 32 + k4 * 4];
        uint32_t* p = &sA[r * 36 + k4 * 4];
        p[0] = f2tf(v.x); p[1] = f2tf(v.y); p[2] = f2tf(v.z); p[3] = f2tf(v.w);
    }
    for (int l = tid; l < 3072; l += 256) {            // 32 k x 96 c
        int c = l % 96, k = l / 96, g = c >> 5;
        sB[c * 36 + k] = f2tf(Wx2h[(n * 32 + k) * 768 + g * 256 + h0 + (c & 31)]);
    }
    __syncthreads();
    #pragma unroll
    for (int ks = 0; ks < 4; ks++) {
        int k0 = ks * 8;
        const uint32_t* ap = &sA[(wm * 16 + lr) * 36 + k0 + lc];
        uint32_t a0 = ap[0], a1 = ap[8 * 36], a2 = ap[4], a3 = ap[8 * 36 + 4];
        #pragma unroll
        for (int g = 0; g < 3; g++)
            #pragma unroll
            for (int j = 0; j < 2; j++) {
                const uint32_t* bp = &sB[(g * 32 + wn * 16 + j * 8 + lr) * 36 + k0 + lc];
                mma8(gx[j][g], a0, a1, a2, a3, bp[0], bp[4]);
            }
    }
    __syncthreads();

    // ---- phase 2: gate_h (K = 256, A = hs, B = Wh2h) ----
    for (int kt = 0; kt < 8; kt++) {
        for (int l = tid; l < 512; l += 256) {
            int r = l >> 3, k4 = l & 7;
            float4 v = *(const float4*)&hs[((b0 + r) * NBLK + n) * 256 + kt * 32 + k4 * 4];
            uint32_t* p = &sA[r * 36 + k4 * 4];
            p[0] = f2tf(v.x); p[1] = f2tf(v.y); p[2] = f2tf(v.z); p[3] = f2tf(v.w);
        }
        for (int l = tid; l < 3072; l += 256) {
            int c = l % 96, k = l / 96, g = c >> 5;
            sB[c * 36 + k] = f2tf(Wh2h[(n * 256 + kt * 32 + k) * 768 + g * 256 + h0 + (c & 31)]);
        }
        __syncthreads();
        #pragma unroll
        for (int ks = 0; ks < 4; ks++) {
            int k0 = ks * 8;
            const uint32_t* ap = &sA[(wm * 16 + lr) * 36 + k0 + lc];
            uint32_t a0 = ap[0], a1 = ap[8 * 36], a2 = ap[4], a3 = ap[8 * 36 + 4];
            #pragma unroll
            for (int g = 0; g < 3; g++)
                #pragma unroll
                for (int j = 0; j < 2; j++) {
                    const uint32_t* bp = &sB[(g * 32 + wn * 16 + j * 8 + lr) * 36 + k0 + lc];
                    mma8(gh[j][g], a0, a1, a2, a3, bp[0], bp[4]);
                }
        }
        __syncthreads();
    }

    // ---- epilogue: GRU update (thread-local) ----
    #pragma unroll
    for (int j = 0; j < 2; j++) {
        int hcol = h0 + wn * 16 + j * 8 + 2 * lc;
        #pragma unroll
        for (int half = 0; half < 2; half++) {
            int brow = b0 + wm * 16 + lr + half * 8;
            int idx = (brow * NBLK + n) * HDIM + hcol;
            float2 hold = *(const float2*)&hs[idx];
            float r0 = sigf(gx[j][0][half * 2 + 0] + gh[j][0][half * 2 + 0]);
            float r1 = sigf(gx[j][0][half * 2 + 1] + gh[j][0][half * 2 + 1]);
            float z0 = sigf(gx[j][1][half * 2 + 0] + gh[j][1][half * 2 + 0]);
            float z1 = sigf(gx[j][1][half * 2 + 1] + gh[j][1][half * 2 + 1]);
            float n0 = tanhf(gx[j][2][half * 2 + 0] + r0 * gh[j][2][half * 2 + 0]);
            float n1 = tanhf(gx[j][2][half * 2 + 1] + r1 * gh[j][2][half * 2 + 1]);
            float2 o;
            o.x = n0 + z0 * (hold.x - n0);
            o.y = n1 + z1 * (hold.y - n1);
            *(float2*)&g_hsnew[idx] = o;
        }
    }
}

// ======== generic 128x64 tf32 GEMM bodies (k3a1 / k3b / k3d) =============
// 8 warps: wm=warp>>1 (32 rows), wn=warp&1 (32 cols); warp = 2x4 m16n8 frags
#define GEMM_PROLOG() \
    const int n  = blockIdx.z; \
    const int b0 = blockIdx.x * 128; \
    const int tid = threadIdx.x, warp = tid >> 5, lane = tid & 31; \
    const int wm = warp >> 1, wn = warp & 1; \
    const int lr = lane >> 2, lc = lane & 3; \
    __shared__ uint32_t sA[128 * 36]; \
    __shared__ uint32_t sB[64 * 36]; \
    float acc[2][4][4] = {};

#define GEMM_LOAD_A(SRC, LD) \
    for (int l = tid; l < 1024; l += 256) { \
        int r = l >> 3, k4 = l & 7; \
        float4 v = *(const float4*)&(SRC)[((b0 + r) * NBLK + n) * (LD) + kt * 32 + k4 * 4]; \
        uint32_t* p = &sA[r * 36 + k4 * 4]; \
        p[0] = f2tf(v.x); p[1] = f2tf(v.y); p[2] = f2tf(v.z); p[3] = f2tf(v.w); \
    }

#define GEMM_MMA() \
    __syncthreads(); \
    _Pragma("unroll") \
    for (int ks = 0; ks < 4; ks++) { \
        int k0 = ks * 8; \
        uint32_t a[2][4]; \
        _Pragma("unroll") \
        for (int mi = 0; mi < 2; mi++) { \
            const uint32_t* ap = &sA[(wm * 32 + mi * 16 + lr) * 36 + k0 + lc]; \
            a[mi][0] = ap[0]; a[mi][1] = ap[8 * 36]; a[mi][2] = ap[4]; a[mi][3] = ap[8 * 36 + 4]; \
        } \
        _Pragma("unroll") \
        for (int ni = 0; ni < 4; ni++) { \
            const uint32_t* bp = &sB[(wn * 32 + ni * 8 + lr) * 36 + k0 + lc]; \
            uint32_t b0f = bp[0], b1f = bp[4]; \
            mma8(acc[0][ni], a[0][0], a[0][1], a[0][2], a[0][3], b0f, b1f); \
            mma8(acc[1][ni], a[1][0], a[1][1], a[1][2], a[1][3], b0f, b1f); \
        } \
    } \
    __syncthreads();

// ---- k3a1: q2/k2 (K=256; B cols 0..31 -> Wq_, 32..63 -> Wk_) ----
__global__ __launch_bounds__(256) void k3a1_qk(
    const float* __restrict__ Wq_, const float* __restrict__ Wk_)
{
    GEMM_PROLOG();
    for (int kt = 0; kt < 8; kt++) {
        GEMM_LOAD_A(g_hsnew, 256);
        for (int l = tid; l < 2048; l += 256) {
            int c = l & 63, k = l >> 6;
            int kk = (n * 256 + kt * 32 + k) * 32;
            sB[c * 36 + k] = f2tf((c < 32) ? Wq_[kk + c] : Wk_[kk + c - 32]);
        }
        GEMM_MMA();
    }
    #pragma unroll
    for (int mi = 0; mi < 2; mi++)
        #pragma unroll
        for (int ni = 0; ni < 4; ni++) {
            int col = wn * 32 + ni * 8 + 2 * lc;
            float* dst = (col < 32) ? g_q2 : g_k2;
            int cc = col & 31;
            #pragma unroll
            for (int half = 0; half < 2; half++) {
                int brow = b0 + wm * 32 + mi * 16 + lr + half * 8;
                float2 v = make_float2(acc[mi][ni][half * 2], acc[mi][ni][half * 2 + 1]);
                *(float2*)&dst[(brow * NBLK + n) * 32 + cc] = v;
            }
        }
}

// ---- k3b: v2 = hs_new @ Wv_ (K=256, 16 col-tiles) ----
__global__ __launch_bounds__(256) void k3b_v2(const float* __restrict__ Wv_)
{
    GEMM_PROLOG();
    const int o0 = blockIdx.y * 64;
    for (int kt = 0; kt < 8; kt++) {
        GEMM_LOAD_A(g_hsnew, 256);
        for (int l = tid; l < 2048; l += 256) {
            int c = l & 63, k = l >> 6;
            sB[c * 36 + k] = f2tf(Wv_[(n * 256 + kt * 32 + k) * 1024 + o0 + c]);
        }
        GEMM_MMA();
    }
    #pragma unroll
    for (int mi = 0; mi < 2; mi++)
        #pragma unroll
        for (int ni = 0; ni < 4; ni++) {
            int col = o0 + wn * 32 + ni * 8 + 2 * lc;
            #pragma unroll
            for (int half = 0; half < 2; half++) {
                int brow = b0 + wm * 32 + mi * 16 + lr + half * 8;
                float2 v = make_float2(acc[mi][ni][half * 2], acc[mi][ni][half * 2 + 1]);
                *(float2*)&g_v2[(brow * NBLK + n) * 1024 + col] = v;
            }
        }
}

// ---- k3d: out = mask*(ctx@Wout + hs_new) + (1-mask)*hs (K=1024) ----
__global__ __launch_bounds__(256) void k3d_out(
    const float* __restrict__ Wout, const float* __restrict__ hs,
    float* __restrict__ out)
{
    GEMM_PROLOG();
    const int o0 = blockIdx.y * 64;
    for (int kt = 0; kt < 32; kt++) {
        GEMM_LOAD_A(g_ctx, 1024);
        for (int l = tid; l < 2048; l += 256) {
            int c = l & 63, k = l >> 6;
            sB[c * 36 + k] = f2tf(Wout[(n * 1024 + kt * 32 + k) * 256 + o0 + c]);
        }
        GEMM_MMA();
    }
    #pragma unroll
    for (int mi = 0; mi < 2; mi++)
        #pragma unroll
        for (int ni = 0; ni < 4; ni++) {
            int col = o0 + wn * 32 + ni * 8 + 2 * lc;
            #pragma unroll
            for (int half = 0; half < 2; half++) {
                int brow = b0 + wm * 32 + mi * 16 + lr + half * 8;
                float m = g_mask[brow * NBLK + n];
                int idx = (brow * NBLK + n) * HDIM + col;
                float2 hn = *(const float2*)&g_hsnew[idx];
                float2 ho = *(const float2*)&hs[idx];
                float2 r;
                r.x = m * (acc[mi][ni][half * 2]     + hn.x) + (1.f - m) * ho.x;
                r.y = m * (acc[mi][ni][half * 2 + 1] + hn.y) + (1.f - m) * ho.y;
                *(float2*)&out[idx] = r;
            }
        }
}

// ================= Kernel 3a2: 4-head 8x8 attention (SIMT) ===============
__global__ __launch_bounds__(256) void k3a2_att()
{
    const int w = threadIdx.x >> 5, lane = threadIdx.x & 31;
    const int b = blockIdx.x * 8 + w;

    __shared__ float sQ[8][256];
    __shared__ float sK[8][256];
    for (int l = lane; l < 256; l += 32) {
        sQ[w][l] = g_q2[b * 256 + l];
        sK[w][l] = g_k2[b * 256 + l];
    }
    __syncwarp();

    const int h = lane >> 3, nq = lane & 7;
    float sc[8], mx = -1e30f;
    #pragma unroll
    for (int m = 0; m < 8; m++) {
        float s = 0.f;
        #pragma unroll
        for (int dk = 0; dk < 8; dk++)
            s += sQ[w][nq * 32 + h * 8 + dk] * sK[w][m * 32 + h * 8 + dk];
        s *= 0.35355339059327373f;
        sc[m] = s;
        mx = fmaxf(mx, s);
    }
    float den = 0.f;
    #pragma unroll
    for (int m = 0; m < 8; m++) { sc[m] = expf(sc[m] - mx); den += sc[m]; }
    float scale = g_mask[b * NBLK + nq] / den;
    #pragma unroll
    for (int m = 0; m < 8; m++)
        g_att[((b * NHC + h) * NBLK + nq) * NBLK + m] = sc[m] * scale;
}

// ================= Kernel 3c: ctx = att @ v2 (SIMT, float4) ==============
__global__ __launch_bounds__(256) void k3c_ctx()
{
    const int b = blockIdx.x;
    __shared__ float4 sV[2048];
    __shared__ float sAtt[256];

    const float4* vb = (const float4*)(g_v2 + b * 8192);
    for (int l = threadIdx.x; l < 2048; l += 256) sV[l] = vb[l];
    sAtt[threadIdx.x] = g_att[b * 256 + threadIdx.x];
    __syncthreads();

    float4* cb = (float4*)(g_ctx + b * 8192);
    for (int l = threadIdx.x; l < 2048; l += 256) {
        int nq = l >> 8, c4 = l & 255, g = c4 >> 6;
        const float* ap = &sAtt[(g * 8 + nq) * 8];
        float4 acc = make_float4(0.f, 0.f, 0.f, 0.f);
        #pragma unroll
        for (int m = 0; m < 8; m++) {
            float a = ap[m];
            float4 v = sV[m * 256 + c4];
            acc.x += a * v.x; acc.y += a * v.y; acc.z += a * v.z; acc.w += a * v.w;
        }
        cb[l] = acc;
    }
}

// =========================== launch ======================================
extern "C" void kernel_launch(void* const* d_in, const int* in_sizes, int n_in,
                              void* d_out, int out_size)
{
    const float* x1   = (const float*)d_in[0];
    const float* x2   = (const float*)d_in[1];
    const float* hs   = (const float*)d_in[2];
    const float* Wkey = (const float*)d_in[3];
    const float* bkey = (const float*)d_in[4];
    const float* Wval = (const float*)d_in[5];
    const float* bval = (const float*)d_in[6];
    const float* Wq   = (const float*)d_in[7];
    const float* Wq_  = (const float*)d_in[8];
    const float* Wk_  = (const float*)d_in[9];
    const float* Wv_  = (const float*)d_in[10];
    const float* Wout = (const float*)d_in[11];
    const float* Wx2h = (const float*)d_in[12];
    const float* Wh2h = (const float*)d_in[13];
    float* out = (float*)d_out;

    k1_gating<<<BSZ / 8, 256>>>(x1, x2, hs, Wkey, bkey, Wval, bval, Wq);
    k2_gru   <<<dim3(BSZ / 64, HDIM / 32, NBLK), 256>>>(hs, Wx2h, Wh2h);
    k3a1_qk  <<<dim3(BSZ / 128, 1, NBLK), 256>>>(Wq_, Wk_);
    k3a2_att <<<BSZ / 8, 256>>>();
    k3b_v2   <<<dim3(BSZ / 128, 16, NBLK), 256>>>(Wv_);
    k3c_ctx  <<<BSZ, 256>>>();
    k3d_out  <<<dim3(BSZ / 128, 4, NBLK), 256>>>(Wout, hs, out);
}

// round 6
// speedup vs baseline: 2.6620x; 1.4741x over previous
#include <cuda_runtime.h>
#include <math.h>
#include <stdint.h>

#define BSZ   8192
#define NBLK  8
#define HDIM  256
#define DDIM  256
#define DKIN  16
#define DVIN  32
#define NHC   4
#define KACT  4

// ---------------- device scratch ----------------
__device__ float g_mask  [BSZ * NBLK];
__device__ float g_inputs[BSZ * NBLK * DVIN];
__device__ float g_hsnew [BSZ * NBLK * HDIM];
__device__ float g_q2    [BSZ * NBLK * 32];
__device__ float g_k2    [BSZ * NBLK * 32];
__device__ float g_v2    [BSZ * NBLK * 1024];
__device__ float g_ctx   [BSZ * NBLK * 1024];

// ---------------- helpers (arch-agnostic PTX, sm_80+) ----------------
__device__ __forceinline__ uint32_t smem_u32(const void* p) {
    uint32_t a;
    asm("{ .reg .u64 t; cvta.to.shared.u64 t, %1; cvt.u32.u64 %0, t; }" : "=r"(a) : "l"(p));
    return a;
}
#define CPA16(dst, src) asm volatile("cp.async.cg.shared.global [%0], [%1], 16;" :: "r"(dst), "l"(src))
#define CPCOMMIT()      asm volatile("cp.async.commit_group;" ::: "memory")
#define CPWAIT1()       asm volatile("cp.async.wait_group 1;" ::: "memory")
#define CPWAIT0()       asm volatile("cp.async.wait_group 0;" ::: "memory")

// raw fp32 bits as tf32 operands (hardware truncates low mantissa bits)
__device__ __forceinline__ void mma8(float* d, uint32_t a0, uint32_t a1, uint32_t a2,
                                     uint32_t a3, uint32_t b0, uint32_t b1) {
    asm volatile("mma.sync.aligned.m16n8k8.row.col.f32.tf32.tf32.f32 "
        "{%0,%1,%2,%3}, {%4,%5,%6,%7}, {%8,%9}, {%0,%1,%2,%3};"
        : "+f"(d[0]), "+f"(d[1]), "+f"(d[2]), "+f"(d[3])
        : "r"(a0), "r"(a1), "r"(a2), "r"(a3), "r"(b0), "r"(b1));
}
__device__ __forceinline__ float sigf(float x) { return 1.f / (1.f + expf(-x)); }
__device__ __forceinline__ uint32_t fu(float x) { return __float_as_uint(x); }

// ================= Kernel 1: gating attention, mask, inputs ==============
__global__ __launch_bounds__(256) void k1_gating(
    const float* __restrict__ x1, const float* __restrict__ x2,
    const float* __restrict__ hs,
    const float* __restrict__ Wkey, const float* __restrict__ bkey,
    const float* __restrict__ Wval, const float* __restrict__ bval,
    const float* __restrict__ Wq)
{
    const int w    = threadIdx.x >> 5;
    const int lane = threadIdx.x & 31;
    const int b    = blockIdx.x * 8 + w;

    __shared__ float sKL[8][48];
    __shared__ float sVL[8][96];
    __shared__ float sQL[8][128];
    __shared__ float sS [8][24];
    __shared__ float sM [8][8];

    for (int o = lane; o < 48; o += 32) {
        int s = o >> 4, j = o & 15;
        float a0 = 0.f, a1 = 0.f, a2 = 0.f, a3 = 0.f;
        if (s < 2) {
            const float* xp = s ? (x2 + b * DDIM) : (x1 + b * DDIM);
            const float* wp = Wkey + j;
            #pragma unroll 4
            for (int d = 0; d < DDIM; d += 4) {
                a0 += xp[d]     * wp[d * 16];
                a1 += xp[d + 1] * wp[(d + 1) * 16];
                a2 += xp[d + 2] * wp[(d + 2) * 16];
                a3 += xp[d + 3] * wp[(d + 3) * 16];
            }
        }
        sKL[w][o] = bkey[j] + ((a0 + a1) + (a2 + a3));
    }
    for (int o = lane; o < 96; o += 32) {
        int s = o >> 5, j = o & 31;
        float a0 = 0.f, a1 = 0.f, a2 = 0.f, a3 = 0.f;
        if (s < 2) {
            const float* xp = s ? (x2 + b * DDIM) : (x1 + b * DDIM);
            const float* wp = Wval + j;
            #pragma unroll 4
            for (int d = 0; d < DDIM; d += 4) {
                a0 += xp[d]     * wp[d * 32];
                a1 += xp[d + 1] * wp[(d + 1) * 32];
                a2 += xp[d + 2] * wp[(d + 2) * 32];
                a3 += xp[d + 3] * wp[(d + 3) * 32];
            }
        }
        sVL[w][o] = bval[j] + ((a0 + a1) + (a2 + a3));
    }
    for (int o = lane; o < 128; o += 32) {
        int nn = o >> 4, j = o & 15;
        const float* hp = hs + (b * NBLK + nn) * HDIM;
        const float* wp = Wq + nn * HDIM * DKIN + j;
        float a0 = 0.f, a1 = 0.f, a2 = 0.f, a3 = 0.f;
        #pragma unroll 4
        for (int d = 0; d < DDIM; d += 4) {
            a0 += hp[d]     * wp[d * 16];
            a1 += hp[d + 1] * wp[(d + 1) * 16];
            a2 += hp[d + 2] * wp[(d + 2) * 16];
            a3 += hp[d + 3] * wp[(d + 3) * 16];
        }
        sQL[w][o] = (a0 + a1) + (a2 + a3);
    }
    __syncwarp();

    for (int o = lane; o < 24; o += 32) {
        int nn = o / 3, s = o % 3;
        float acc = 0.f;
        #pragma unroll
        for (int j = 0; j < 16; j++) acc += sQL[w][nn * 16 + j] * sKL[w][s * 16 + j];
        sS[w][o] = acc * 0.25f;
    }
    __syncwarp();

    if (lane < 8) {
        float nu = sS[w][lane * 3 + 2];
        int rank = 0;
        #pragma unroll
        for (int n2 = 0; n2 < 8; n2++) {
            float nu2 = sS[w][n2 * 3 + 2];
            rank += (nu2 > nu) || (nu2 == nu && n2 < lane);
        }
        float m = (rank < (NBLK - KACT)) ? 0.f : 1.f;
        sM[w][lane] = m;
        g_mask[b * NBLK + lane] = m;
    }
    __syncwarp();

    for (int o = lane; o < 256; o += 32) {
        int nn = o >> 5, j = o & 31;
        float s0 = sS[w][nn * 3 + 0], s1 = sS[w][nn * 3 + 1], s2 = sS[w][nn * 3 + 2];
        float mx = fmaxf(s0, fmaxf(s1, s2));
        float e0 = expf(s0 - mx), e1 = expf(s1 - mx), e2 = expf(s2 - mx);
        float inv = 1.f / (e0 + e1 + e2);
        float val = (e0 * sVL[w][j] + e1 * sVL[w][32 + j] + e2 * sVL[w][64 + j])
                    * inv * sM[w][nn];
        g_inputs[(b * NBLK + nn) * DVIN + j] = val;
    }
}

// ================= Kernel 2: fused GRU (tf32 mma, cp.async pipeline) =====
// grid (128, 8, 8): tile 64 rows x 32 h (x3 gates). 8 warps: wm=warp>>1
// (16 rows), wn=warp&1 (16 h, all 3 gates). A[row][k] s36, B[k][col] s104.
__global__ __launch_bounds__(256) void k2_gru(
    const float* __restrict__ hs,
    const float* __restrict__ Wx2h,
    const float* __restrict__ Wh2h)
{
    const int n  = blockIdx.z;
    const int b0 = blockIdx.x * 64;
    const int h0 = blockIdx.y * 32;
    const int tid = threadIdx.x, warp = tid >> 5, lane = tid & 31;
    const int wm = warp >> 1, wn = warp & 1;
    const int lr = lane >> 2, lc = lane & 3;

    __shared__ float sA[2][64 * 36];
    __shared__ float sB[2][32 * 104];
    uint32_t aB = smem_u32(sA), bB = smem_u32(sB);

    float gx[2][3][4] = {}, gh[2][3][4] = {};

    // ---- phase 1: gate_x (K=32, synchronous fill of buffer 0) ----
    for (int l = tid; l < 2048; l += 256) {
        int r = l >> 5, k = l & 31;
        sA[0][r * 36 + k] = g_inputs[((b0 + r) * NBLK + n) * 32 + k];
    }
    for (int l = tid; l < 3072; l += 256) {
        int k = l / 96, c = l % 96, g = c >> 5;
        sB[0][k * 104 + c] = Wx2h[(n * 32 + k) * 768 + g * 256 + h0 + (c & 31)];
    }
    __syncthreads();
    #pragma unroll
    for (int ks = 0; ks < 4; ks++) {
        int k0 = ks * 8;
        const float* ap = &sA[0][(wm * 16 + lr) * 36 + k0 + lc];
        uint32_t a0 = fu(ap[0]), a1 = fu(ap[8 * 36]), a2 = fu(ap[4]), a3 = fu(ap[8 * 36 + 4]);
        #pragma unroll
        for (int g = 0; g < 3; g++)
            #pragma unroll
            for (int j = 0; j < 2; j++) {
                int col = g * 32 + wn * 16 + j * 8 + lr;
                uint32_t b0f = fu(sB[0][(k0 + lc) * 104 + col]);
                uint32_t b1f = fu(sB[0][(k0 + lc + 4) * 104 + col]);
                mma8(gx[j][g], a0, a1, a2, a3, b0f, b1f);
            }
    }
    __syncthreads();

    // ---- phase 2: gate_h (K=256, 8 K-tiles, double-buffered cp.async) ----
    #define K2_ISSUE(kt, st) { \
        for (int l = tid; l < 512; l += 256) { int r = l >> 3, k4 = l & 7; \
            CPA16(aB + ((st) * 64 * 36 + r * 36 + k4 * 4) * 4, \
                  &hs[((b0 + r) * NBLK + n) * 256 + (kt) * 32 + k4 * 4]); } \
        for (int l = tid; l < 768; l += 256) { int k = l / 24, c4 = l % 24; \
            int c = c4 * 4, g = c >> 5; \
            CPA16(bB + ((st) * 32 * 104 + k * 104 + c) * 4, \
                  &Wh2h[(n * 256 + (kt) * 32 + k) * 768 + g * 256 + h0 + (c & 31)]); } \
        CPCOMMIT(); }

    K2_ISSUE(0, 0);
    for (int kt = 0; kt < 8; kt++) {
        if (kt < 7) { K2_ISSUE(kt + 1, (kt + 1) & 1); CPWAIT1(); }
        else CPWAIT0();
        __syncthreads();
        const float* A  = sA[kt & 1];
        const float* Bt = sB[kt & 1];
        #pragma unroll
        for (int ks = 0; ks < 4; ks++) {
            int k0 = ks * 8;
            const float* ap = &A[(wm * 16 + lr) * 36 + k0 + lc];
            uint32_t a0 = fu(ap[0]), a1 = fu(ap[8 * 36]), a2 = fu(ap[4]), a3 = fu(ap[8 * 36 + 4]);
            #pragma unroll
            for (int g = 0; g < 3; g++)
                #pragma unroll
                for (int j = 0; j < 2; j++) {
                    int col = g * 32 + wn * 16 + j * 8 + lr;
                    uint32_t b0f = fu(Bt[(k0 + lc) * 104 + col]);
                    uint32_t b1f = fu(Bt[(k0 + lc + 4) * 104 + col]);
                    mma8(gh[j][g], a0, a1, a2, a3, b0f, b1f);
                }
        }
        __syncthreads();
    }

    // ---- epilogue: GRU update ----
    #pragma unroll
    for (int j = 0; j < 2; j++) {
        int hcol = h0 + wn * 16 + j * 8 + 2 * lc;
        #pragma unroll
        for (int half = 0; half < 2; half++) {
            int brow = b0 + wm * 16 + lr + half * 8;
            int idx = (brow * NBLK + n) * HDIM + hcol;
            float2 hold = *(const float2*)&hs[idx];
            float r0 = sigf(gx[j][0][half * 2 + 0] + gh[j][0][half * 2 + 0]);
            float r1 = sigf(gx[j][0][half * 2 + 1] + gh[j][0][half * 2 + 1]);
            float z0 = sigf(gx[j][1][half * 2 + 0] + gh[j][1][half * 2 + 0]);
            float z1 = sigf(gx[j][1][half * 2 + 1] + gh[j][1][half * 2 + 1]);
            float n0 = tanhf(gx[j][2][half * 2 + 0] + r0 * gh[j][2][half * 2 + 0]);
            float n1 = tanhf(gx[j][2][half * 2 + 1] + r1 * gh[j][2][half * 2 + 1]);
            float2 o;
            o.x = n0 + z0 * (hold.x - n0);
            o.y = n1 + z1 * (hold.y - n1);
            *(float2*)&g_hsnew[idx] = o;
        }
    }
}

// ======== generic 64x64 tf32 GEMM (cp.async double-buffered) =============
// 8 warps: wm=warp>>1 (16 rows), wn=warp&1 (32 cols = 4 m16n8 frags)
#define GEMM_PROLOG() \
    const int n  = blockIdx.z; \
    const int b0 = blockIdx.x * 64; \
    const int tid = threadIdx.x, warp = tid >> 5, lane = tid & 31; \
    const int wm = warp >> 1, wn = warp & 1; \
    const int lr = lane >> 2, lc = lane & 3; \
    __shared__ float sA[2][64 * 36]; \
    __shared__ float sB[2][32 * 72]; \
    uint32_t aB = smem_u32(sA), bB = smem_u32(sB); \
    float acc[4][4] = {};

#define ISSUE_A(kt, st, SRC, LD) \
    for (int l = tid; l < 512; l += 256) { int r = l >> 3, k4 = l & 7; \
        CPA16(aB + ((st) * 64 * 36 + r * 36 + k4 * 4) * 4, \
              &(SRC)[((b0 + r) * NBLK + n) * (LD) + (kt) * 32 + k4 * 4]); }

#define GEMM_MMA(buf) \
    { const float* A = sA[buf]; const float* Bt = sB[buf]; \
      _Pragma("unroll") \
      for (int ks = 0; ks < 4; ks++) { \
          int k0 = ks * 8; \
          const float* ap = &A[(wm * 16 + lr) * 36 + k0 + lc]; \
          uint32_t a0 = fu(ap[0]), a1 = fu(ap[8 * 36]), a2 = fu(ap[4]), a3 = fu(ap[8 * 36 + 4]); \
          _Pragma("unroll") \
          for (int ni = 0; ni < 4; ni++) { \
              int col = wn * 32 + ni * 8 + lr; \
              uint32_t b0f = fu(Bt[(k0 + lc) * 72 + col]); \
              uint32_t b1f = fu(Bt[(k0 + lc + 4) * 72 + col]); \
              mma8(acc[ni], a0, a1, a2, a3, b0f, b1f); \
          } \
      } }

// ---- k3a1: q2/k2 (K=256; cols 0..31 -> Wq_, 32..63 -> Wk_) ----
__global__ __launch_bounds__(256) void k3a1_qk(
    const float* __restrict__ Wq_, const float* __restrict__ Wk_)
{
    GEMM_PROLOG();
    #define A1_ISSUE(kt, st) { \
        ISSUE_A(kt, st, g_hsnew, 256); \
        for (int l = tid; l < 512; l += 256) { int k = l >> 4, c4 = l & 15; \
            const float* src = (c4 < 8) ? &Wq_[(n * 256 + (kt) * 32 + k) * 32 + c4 * 4] \
                                        : &Wk_[(n * 256 + (kt) * 32 + k) * 32 + (c4 - 8) * 4]; \
            CPA16(bB + ((st) * 32 * 72 + k * 72 + c4 * 4) * 4, src); } \
        CPCOMMIT(); }
    A1_ISSUE(0, 0);
    for (int kt = 0; kt < 8; kt++) {
        if (kt < 7) { A1_ISSUE(kt + 1, (kt + 1) & 1); CPWAIT1(); }
        else CPWAIT0();
        __syncthreads();
        GEMM_MMA(kt & 1);
        __syncthreads();
    }
    #pragma unroll
    for (int ni = 0; ni < 4; ni++) {
        int col = wn * 32 + ni * 8 + 2 * lc;
        float* dst = (col < 32) ? g_q2 : g_k2;
        int cc = col & 31;
        int r0 = b0 + wm * 16 + lr, r1 = r0 + 8;
        *(float2*)&dst[(r0 * NBLK + n) * 32 + cc] = make_float2(acc[ni][0], acc[ni][1]);
        *(float2*)&dst[(r1 * NBLK + n) * 32 + cc] = make_float2(acc[ni][2], acc[ni][3]);
    }
}

// ---- k3b: v2 = hs_new @ Wv_ (K=256, 16 col-tiles) ----
__global__ __launch_bounds__(256) void k3b_v2(const float* __restrict__ Wv_)
{
    GEMM_PROLOG();
    const int o0 = blockIdx.y * 64;
    #define B_ISSUE(kt, st) { \
        ISSUE_A(kt, st, g_hsnew, 256); \
        for (int l = tid; l < 512; l += 256) { int k = l >> 4, c4 = l & 15; \
            CPA16(bB + ((st) * 32 * 72 + k * 72 + c4 * 4) * 4, \
                  &Wv_[(n * 256 + (kt) * 32 + k) * 1024 + o0 + c4 * 4]); } \
        CPCOMMIT(); }
    B_ISSUE(0, 0);
    for (int kt = 0; kt < 8; kt++) {
        if (kt < 7) { B_ISSUE(kt + 1, (kt + 1) & 1); CPWAIT1(); }
        else CPWAIT0();
        __syncthreads();
        GEMM_MMA(kt & 1);
        __syncthreads();
    }
    #pragma unroll
    for (int ni = 0; ni < 4; ni++) {
        int col = o0 + wn * 32 + ni * 8 + 2 * lc;
        int r0 = b0 + wm * 16 + lr, r1 = r0 + 8;
        *(float2*)&g_v2[(r0 * NBLK + n) * 1024 + col] = make_float2(acc[ni][0], acc[ni][1]);
        *(float2*)&g_v2[(r1 * NBLK + n) * 1024 + col] = make_float2(acc[ni][2], acc[ni][3]);
    }
}

// ---- k3d: out = mask*(ctx@Wout + hs_new) + (1-mask)*hs (K=1024) ----
__global__ __launch_bounds__(256) void k3d_out(
    const float* __restrict__ Wout, const float* __restrict__ hs,
    float* __restrict__ out)
{
    GEMM_PROLOG();
    const int o0 = blockIdx.y * 64;
    #define D_ISSUE(kt, st) { \
        ISSUE_A(kt, st, g_ctx, 1024); \
        for (int l = tid; l < 512; l += 256) { int k = l >> 4, c4 = l & 15; \
            CPA16(bB + ((st) * 32 * 72 + k * 72 + c4 * 4) * 4, \
                  &Wout[(n * 1024 + (kt) * 32 + k) * 256 + o0 + c4 * 4]); } \
        CPCOMMIT(); }
    D_ISSUE(0, 0);
    for (int kt = 0; kt < 32; kt++) {
        if (kt < 31) { D_ISSUE(kt + 1, (kt + 1) & 1); CPWAIT1(); }
        else CPWAIT0();
        __syncthreads();
        GEMM_MMA(kt & 1);
        __syncthreads();
    }
    #pragma unroll
    for (int ni = 0; ni < 4; ni++) {
        int col = o0 + wn * 32 + ni * 8 + 2 * lc;
        #pragma unroll
        for (int half = 0; half < 2; half++) {
            int brow = b0 + wm * 16 + lr + half * 8;
            float m = g_mask[brow * NBLK + n];
            int idx = (brow * NBLK + n) * HDIM + col;
            float2 hn = *(const float2*)&g_hsnew[idx];
            float2 ho = *(const float2*)&hs[idx];
            float2 r;
            r.x = m * (acc[ni][half * 2]     + hn.x) + (1.f - m) * ho.x;
            r.y = m * (acc[ni][half * 2 + 1] + hn.y) + (1.f - m) * ho.y;
            *(float2*)&out[idx] = r;
        }
    }
}

// ================= Kernel 3c: fused attention + ctx = att @ v2 ===========
__global__ __launch_bounds__(256) void k3c_ctx()
{
    const int b = blockIdx.x;
    __shared__ float4 sV[2048];
    __shared__ float sQ[256], sK[256], sAtt[256];

    const float4* vb = (const float4*)(g_v2 + b * 8192);
    for (int l = threadIdx.x; l < 2048; l += 256) sV[l] = vb[l];
    sQ[threadIdx.x] = g_q2[b * 256 + threadIdx.x];
    sK[threadIdx.x] = g_k2[b * 256 + threadIdx.x];
    __syncthreads();

    if (threadIdx.x < 32) {
        const int lane = threadIdx.x;
        const int h = lane >> 3, nq = lane & 7;
        float sc[8], mx = -1e30f;
        #pragma unroll
        for (int m = 0; m < 8; m++) {
            float s = 0.f;
            #pragma unroll
            for (int dk = 0; dk < 8; dk++)
                s += sQ[nq * 32 + h * 8 + dk] * sK[m * 32 + h * 8 + dk];
            s *= 0.35355339059327373f;
            sc[m] = s;
            mx = fmaxf(mx, s);
        }
        float den = 0.f;
        #pragma unroll
        for (int m = 0; m < 8; m++) { sc[m] = expf(sc[m] - mx); den += sc[m]; }
        float scale = g_mask[b * NBLK + nq] / den;
        #pragma unroll
        for (int m = 0; m < 8; m++)
            sAtt[(h * 8 + nq) * 8 + m] = sc[m] * scale;
    }
    __syncthreads();

    float4* cb = (float4*)(g_ctx + b * 8192);
    for (int l = threadIdx.x; l < 2048; l += 256) {
        int nq = l >> 8, c4 = l & 255, g = c4 >> 6;
        const float* ap = &sAtt[(g * 8 + nq) * 8];
        float4 acc = make_float4(0.f, 0.f, 0.f, 0.f);
        #pragma unroll
        for (int m = 0; m < 8; m++) {
            float a = ap[m];
            float4 v = sV[m * 256 + c4];
            acc.x += a * v.x; acc.y += a * v.y; acc.z += a * v.z; acc.w += a * v.w;
        }
        cb[l] = acc;
    }
}

// =========================== launch ======================================
extern "C" void kernel_launch(void* const* d_in, const int* in_sizes, int n_in,
                              void* d_out, int out_size)
{
    const float* x1   = (const float*)d_in[0];
    const float* x2   = (const float*)d_in[1];
    const float* hs   = (const float*)d_in[2];
    const float* Wkey = (const float*)d_in[3];
    const float* bkey = (const float*)d_in[4];
    const float* Wval = (const float*)d_in[5];
    const float* bval = (const float*)d_in[6];
    const float* Wq   = (const float*)d_in[7];
    const float* Wq_  = (const float*)d_in[8];
    const float* Wk_  = (const float*)d_in[9];
    const float* Wv_  = (const float*)d_in[10];
    const float* Wout = (const float*)d_in[11];
    const float* Wx2h = (const float*)d_in[12];
    const float* Wh2h = (const float*)d_in[13];
    float* out = (float*)d_out;

    k1_gating<<<BSZ / 8, 256>>>(x1, x2, hs, Wkey, bkey, Wval, bval, Wq);
    k2_gru   <<<dim3(BSZ / 64, HDIM / 32, NBLK), 256>>>(hs, Wx2h, Wh2h);
    k3a1_qk  <<<dim3(BSZ / 64, 1, NBLK), 256>>>(Wq_, Wk_);
    k3b_v2   <<<dim3(BSZ / 64, 16, NBLK), 256>>>(Wv_);
    k3c_ctx  <<<BSZ, 256>>>();
    k3d_out  <<<dim3(BSZ / 64, 4, NBLK), 256>>>(Wout, hs, out);
}

// round 7
// speedup vs baseline: 3.7216x; 1.3980x over previous
#include <cuda_runtime.h>
#include <math.h>
#include <stdint.h>

#define BSZ   8192
#define NBLK  8
#define HDIM  256
#define DDIM  256
#define DKIN  16
#define DVIN  32
#define NHC   4
#define KACT  4

// ---------------- device scratch ----------------
__device__ float g_mask  [BSZ * NBLK];
__device__ float g_inputs[BSZ * NBLK * DVIN];
__device__ float g_hsnew [BSZ * NBLK * HDIM];
__device__ float g_q2    [BSZ * NBLK * 32];
__device__ float g_k2    [BSZ * NBLK * 32];
__device__ float g_v2    [BSZ * NBLK * 1024];
__device__ float g_ctx   [BSZ * NBLK * 1024];
__device__ float g_kv    [BSZ * 2 * 48];
__device__ float g_ql    [BSZ * NBLK * 16];

// ---------------- helpers (arch-agnostic PTX, sm_80+) ----------------
__device__ __forceinline__ uint32_t smem_u32(const void* p) {
    uint32_t a;
    asm("{ .reg .u64 t; cvta.to.shared.u64 t, %1; cvt.u32.u64 %0, t; }" : "=r"(a) : "l"(p));
    return a;
}
#define CPA16(dst, src) asm volatile("cp.async.cg.shared.global [%0], [%1], 16;" :: "r"(dst), "l"(src))
#define CPCOMMIT()      asm volatile("cp.async.commit_group;" ::: "memory")
#define CPWAIT1()       asm volatile("cp.async.wait_group 1;" ::: "memory")
#define CPWAIT0()       asm volatile("cp.async.wait_group 0;" ::: "memory")

__device__ __forceinline__ void mma8(float* d, uint32_t a0, uint32_t a1, uint32_t a2,
                                     uint32_t a3, uint32_t b0, uint32_t b1) {
    asm volatile("mma.sync.aligned.m16n8k8.row.col.f32.tf32.tf32.f32 "
        "{%0,%1,%2,%3}, {%4,%5,%6,%7}, {%8,%9}, {%0,%1,%2,%3};"
        : "+f"(d[0]), "+f"(d[1]), "+f"(d[2]), "+f"(d[3])
        : "r"(a0), "r"(a1), "r"(a2), "r"(a3), "r"(b0), "r"(b1));
}
__device__ __forceinline__ float sigf(float x) { return 1.f / (1.f + expf(-x)); }
__device__ __forceinline__ uint32_t fu(float x) { return __float_as_uint(x); }

// 32x32-warp-tile MMA step (A stride 36, B stride 72), accumulators acc[2][4][4]
#define MMA_32x32(A_, B_) \
    _Pragma("unroll") for (int ks = 0; ks < 4; ks++) { \
        int k0 = ks * 8; \
        uint32_t a[2][4]; \
        _Pragma("unroll") for (int mi = 0; mi < 2; mi++) { \
            const float* ap = &(A_)[(wm * 32 + mi * 16 + lr) * 36 + k0 + lc]; \
            a[mi][0] = fu(ap[0]); a[mi][1] = fu(ap[288]); \
            a[mi][2] = fu(ap[4]); a[mi][3] = fu(ap[292]); } \
        _Pragma("unroll") for (int ni = 0; ni < 4; ni++) { \
            int col = wn * 32 + ni * 8 + lr; \
            uint32_t b0f = fu((B_)[(k0 + lc) * 72 + col]); \
            uint32_t b1f = fu((B_)[(k0 + lc + 4) * 72 + col]); \
            mma8(acc[0][ni], a[0][0], a[0][1], a[0][2], a[0][3], b0f, b1f); \
            mma8(acc[1][ni], a[1][0], a[1][1], a[1][2], a[1][3], b0f, b1f); } }

// ================= k1a_kv: [kL|vL] = x @ [Wkey|Wval]  (16384 x 48, K=256) =
__global__ __launch_bounds__(256) void k1a_kv(
    const float* __restrict__ x1, const float* __restrict__ x2,
    const float* __restrict__ Wkey, const float* __restrict__ Wval)
{
    extern __shared__ float sm[];
    float* sA = sm;             // 2 * 4608
    float* sB = sm + 2 * 4608;  // 2 * 1792 (32 x 56)
    uint32_t aB = smem_u32(sA), bB = smem_u32(sB);
    const int b0 = blockIdx.x * 128;
    const int tid = threadIdx.x, warp = tid >> 5, lane = tid & 31;
    const int wm = warp >> 1, wn = warp & 1;
    const int lr = lane >> 2, lc = lane & 3;
    float acc[2][3][4] = {};

#define KV_ISSUE(kt, st) { \
    for (int l = tid; l < 1024; l += 256) { int r = l >> 3, k4 = l & 7; \
        int row = b0 + r; const float* src = ((row & 1) ? x2 : x1) + (row >> 1) * 256 + (kt) * 32 + k4 * 4; \
        CPA16(aB + ((st) * 4608 + r * 36 + k4 * 4) * 4, src); } \
    for (int l = tid; l < 384; l += 256) { int k = l / 12, c4 = l % 12; int c = c4 * 4; \
        const float* src = (c < 16) ? &Wkey[((kt) * 32 + k) * 16 + c] : &Wval[((kt) * 32 + k) * 32 + c - 16]; \
        CPA16(bB + ((st) * 1792 + k * 56 + c) * 4, src); } \
    CPCOMMIT(); }

    KV_ISSUE(0, 0);
    for (int kt = 0; kt < 8; kt++) {
        if (kt < 7) { KV_ISSUE(kt + 1, (kt + 1) & 1); CPWAIT1(); }
        else CPWAIT0();
        __syncthreads();
        const float* A_ = sA + (kt & 1) * 4608;
        const float* B_ = sB + (kt & 1) * 1792;
        #pragma unroll
        for (int ks = 0; ks < 4; ks++) {
            int k0 = ks * 8;
            uint32_t a[2][4];
            #pragma unroll
            for (int mi = 0; mi < 2; mi++) {
                const float* ap = &A_[(wm * 32 + mi * 16 + lr) * 36 + k0 + lc];
                a[mi][0] = fu(ap[0]); a[mi][1] = fu(ap[288]);
                a[mi][2] = fu(ap[4]); a[mi][3] = fu(ap[292]);
            }
            #pragma unroll
            for (int ni = 0; ni < 3; ni++) {
                int col = wn * 24 + ni * 8 + lr;
                uint32_t b0f = fu(B_[(k0 + lc) * 56 + col]);
                uint32_t b1f = fu(B_[(k0 + lc + 4) * 56 + col]);
                mma8(acc[0][ni], a[0][0], a[0][1], a[0][2], a[0][3], b0f, b1f);
                mma8(acc[1][ni], a[1][0], a[1][1], a[1][2], a[1][3], b0f, b1f);
            }
        }
        __syncthreads();
    }
    #pragma unroll
    for (int mi = 0; mi < 2; mi++)
        #pragma unroll
        for (int ni = 0; ni < 3; ni++) {
            int col = wn * 24 + ni * 8 + 2 * lc;
            int r0 = b0 + wm * 32 + mi * 16 + lr;
            *(float2*)&g_kv[r0 * 48 + col]       = make_float2(acc[mi][ni][0], acc[mi][ni][1]);
            *(float2*)&g_kv[(r0 + 8) * 48 + col] = make_float2(acc[mi][ni][2], acc[mi][ni][3]);
        }
}

// ================= k1a_ql: qL = hs @ Wq[n]  (8192 x 16 per n, K=256) =====
__global__ __launch_bounds__(256) void k1a_ql(
    const float* __restrict__ hs, const float* __restrict__ Wq)
{
    extern __shared__ float sm[];
    float* sA = sm;             // 2 * 4608
    float* sB = sm + 2 * 4608;  // 2 * 768 (32 x 24)
    uint32_t aB = smem_u32(sA), bB = smem_u32(sB);
    const int n = blockIdx.y, b0 = blockIdx.x * 128;
    const int tid = threadIdx.x, warp = tid >> 5, lane = tid & 31;
    const int wm = warp;
    const int lr = lane >> 2, lc = lane & 3;
    float acc[2][4] = {};

#define QL_ISSUE(kt, st) { \
    for (int l = tid; l < 1024; l += 256) { int r = l >> 3, k4 = l & 7; \
        CPA16(aB + ((st) * 4608 + r * 36 + k4 * 4) * 4, \
              &hs[((b0 + r) * NBLK + n) * 256 + (kt) * 32 + k4 * 4]); } \
    for (int l = tid; l < 128; l += 256) { int k = l >> 2, c4 = l & 3; \
        CPA16(bB + ((st) * 768 + k * 24 + c4 * 4) * 4, \
              &Wq[(n * 256 + (kt) * 32 + k) * 16 + c4 * 4]); } \
    CPCOMMIT(); }

    QL_ISSUE(0, 0);
    for (int kt = 0; kt < 8; kt++) {
        if (kt < 7) { QL_ISSUE(kt + 1, (kt + 1) & 1); CPWAIT1(); }
        else CPWAIT0();
        __syncthreads();
        const float* A_ = sA + (kt & 1) * 4608;
        const float* B_ = sB + (kt & 1) * 768;
        #pragma unroll
        for (int ks = 0; ks < 4; ks++) {
            int k0 = ks * 8;
            const float* ap = &A_[(wm * 16 + lr) * 36 + k0 + lc];
            uint32_t a0 = fu(ap[0]), a1 = fu(ap[288]), a2 = fu(ap[4]), a3 = fu(ap[292]);
            #pragma unroll
            for (int ni = 0; ni < 2; ni++) {
                int col = ni * 8 + lr;
                uint32_t b0f = fu(B_[(k0 + lc) * 24 + col]);
                uint32_t b1f = fu(B_[(k0 + lc + 4) * 24 + col]);
                mma8(acc[ni], a0, a1, a2, a3, b0f, b1f);
            }
        }
        __syncthreads();
    }
    #pragma unroll
    for (int ni = 0; ni < 2; ni++) {
        int col = ni * 8 + 2 * lc;
        int r0 = b0 + wm * 16 + lr;
        *(float2*)&g_ql[(r0 * NBLK + n) * 16 + col]       = make_float2(acc[ni][0], acc[ni][1]);
        *(float2*)&g_ql[((r0 + 8) * NBLK + n) * 16 + col] = make_float2(acc[ni][2], acc[ni][3]);
    }
}

// ================= k1b: scores, top-k mask, softmax, inputs ==============
__global__ __launch_bounds__(256) void k1b_gate(
    const float* __restrict__ bkey, const float* __restrict__ bval)
{
    const int w = threadIdx.x >> 5, lane = threadIdx.x & 31;
    const int b = blockIdx.x * 8 + w;

    __shared__ float sKL[8][48];
    __shared__ float sVL[8][96];
    __shared__ float sQL[8][128];
    __shared__ float sS [8][24];
    __shared__ float sM [8][8];

    for (int o = lane; o < 48; o += 32) {
        int s = o >> 4, j = o & 15;
        sKL[w][o] = bkey[j] + (s < 2 ? g_kv[(b * 2 + s) * 48 + j] : 0.f);
    }
    for (int o = lane; o < 96; o += 32) {
        int s = o >> 5, j = o & 31;
        sVL[w][o] = bval[j] + (s < 2 ? g_kv[(b * 2 + s) * 48 + 16 + j] : 0.f);
    }
    for (int o = lane; o < 128; o += 32) sQL[w][o] = g_ql[b * 128 + o];
    __syncwarp();

    for (int o = lane; o < 24; o += 32) {
        int nn = o / 3, s = o % 3;
        float acc = 0.f;
        #pragma unroll
        for (int j = 0; j < 16; j++) acc += sQL[w][nn * 16 + j] * sKL[w][s * 16 + j];
        sS[w][o] = acc * 0.25f;
    }
    __syncwarp();

    if (lane < 8) {
        float nu = sS[w][lane * 3 + 2];
        int rank = 0;
        #pragma unroll
        for (int n2 = 0; n2 < 8; n2++) {
            float nu2 = sS[w][n2 * 3 + 2];
            rank += (nu2 > nu) || (nu2 == nu && n2 < lane);
        }
        float m = (rank < (NBLK - KACT)) ? 0.f : 1.f;
        sM[w][lane] = m;
        g_mask[b * NBLK + lane] = m;
    }
    __syncwarp();

    for (int o = lane; o < 256; o += 32) {
        int nn = o >> 5, j = o & 31;
        float s0 = sS[w][nn * 3 + 0], s1 = sS[w][nn * 3 + 1], s2 = sS[w][nn * 3 + 2];
        float mx = fmaxf(s0, fmaxf(s1, s2));
        float e0 = expf(s0 - mx), e1 = expf(s1 - mx), e2 = expf(s2 - mx);
        float inv = 1.f / (e0 + e1 + e2);
        float val = (e0 * sVL[w][j] + e1 * sVL[w][32 + j] + e2 * sVL[w][64 + j])
                    * inv * sM[w][nn];
        g_inputs[(b * NBLK + nn) * DVIN + j] = val;
    }
}

// ================= k2: fused GRU (128 rows x 16h x 3 gates) ===============
__global__ __launch_bounds__(256) void k2_gru(
    const float* __restrict__ hs,
    const float* __restrict__ Wx2h,
    const float* __restrict__ Wh2h)
{
    extern __shared__ float sm[];
    float* sA = sm;             // 2 * 4608
    float* sB = sm + 2 * 4608;  // 2 * 1792 (32 x 56)
    uint32_t aB = smem_u32(sA), bB = smem_u32(sB);
    const int n = blockIdx.z, b0 = blockIdx.x * 128, h0 = blockIdx.y * 16;
    const int tid = threadIdx.x, warp = tid >> 5, lane = tid & 31;
    const int wm = warp >> 1, wn = warp & 1;
    const int lr = lane >> 2, lc = lane & 3;

    float gx[2][3][4] = {}, gh[2][3][4] = {};

#define K2_MMA(A_, B_, ACC) \
    _Pragma("unroll") for (int ks = 0; ks < 4; ks++) { \
        int k0 = ks * 8; \
        uint32_t a[2][4]; \
        _Pragma("unroll") for (int mi = 0; mi < 2; mi++) { \
            const float* ap = &(A_)[(wm * 32 + mi * 16 + lr) * 36 + k0 + lc]; \
            a[mi][0] = fu(ap[0]); a[mi][1] = fu(ap[288]); \
            a[mi][2] = fu(ap[4]); a[mi][3] = fu(ap[292]); } \
        _Pragma("unroll") for (int g = 0; g < 3; g++) { \
            int col = g * 16 + wn * 8 + lr; \
            uint32_t b0f = fu((B_)[(k0 + lc) * 56 + col]); \
            uint32_t b1f = fu((B_)[(k0 + lc + 4) * 56 + col]); \
            mma8(ACC[0][g], a[0][0], a[0][1], a[0][2], a[0][3], b0f, b1f); \
            mma8(ACC[1][g], a[1][0], a[1][1], a[1][2], a[1][3], b0f, b1f); } }

    // phase 1: gate_x (K=32, one tile, stage 0)
    for (int l = tid; l < 1024; l += 256) {
        int r = l >> 3, k4 = l & 7;
        CPA16(aB + (r * 36 + k4 * 4) * 4, &g_inputs[((b0 + r) * NBLK + n) * 32 + k4 * 4]);
    }
    for (int l = tid; l < 384; l += 256) {
        int k = l / 12, c4 = l % 12, g = c4 >> 2, cc4 = c4 & 3;
        CPA16(bB + (k * 56 + g * 16 + cc4 * 4) * 4,
              &Wx2h[(n * 32 + k) * 768 + g * 256 + h0 + cc4 * 4]);
    }
    CPCOMMIT(); CPWAIT0();
    __syncthreads();
    K2_MMA(sA, sB, gx);
    __syncthreads();

    // phase 2: gate_h (K=256, 8 K-tiles, double-buffered)
#define K2_ISSUE(kt, st) { \
    for (int l = tid; l < 1024; l += 256) { int r = l >> 3, k4 = l & 7; \
        CPA16(aB + ((st) * 4608 + r * 36 + k4 * 4) * 4, \
              &hs[((b0 + r) * NBLK + n) * 256 + (kt) * 32 + k4 * 4]); } \
    for (int l = tid; l < 384; l += 256) { int k = l / 12, c4 = l % 12, g = c4 >> 2, cc4 = c4 & 3; \
        CPA16(bB + ((st) * 1792 + k * 56 + g * 16 + cc4 * 4) * 4, \
              &Wh2h[(n * 256 + (kt) * 32 + k) * 768 + g * 256 + h0 + cc4 * 4]); } \
    CPCOMMIT(); }

    K2_ISSUE(0, 0);
    for (int kt = 0; kt < 8; kt++) {
        if (kt < 7) { K2_ISSUE(kt + 1, (kt + 1) & 1); CPWAIT1(); }
        else CPWAIT0();
        __syncthreads();
        const float* A_ = sA + (kt & 1) * 4608;
        const float* B_ = sB + (kt & 1) * 1792;
        K2_MMA(A_, B_, gh);
        __syncthreads();
    }

    // epilogue
    #pragma unroll
    for (int mi = 0; mi < 2; mi++)
        #pragma unroll
        for (int half = 0; half < 2; half++) {
            int row = b0 + wm * 32 + mi * 16 + lr + half * 8;
            int idx = (row * NBLK + n) * HDIM + h0 + wn * 8 + 2 * lc;
            float2 hold = *(const float2*)&hs[idx];
            float r0 = sigf(gx[mi][0][half * 2 + 0] + gh[mi][0][half * 2 + 0]);
            float r1 = sigf(gx[mi][0][half * 2 + 1] + gh[mi][0][half * 2 + 1]);
            float z0 = sigf(gx[mi][1][half * 2 + 0] + gh[mi][1][half * 2 + 0]);
            float z1 = sigf(gx[mi][1][half * 2 + 1] + gh[mi][1][half * 2 + 1]);
            float n0 = tanhf(gx[mi][2][half * 2 + 0] + r0 * gh[mi][2][half * 2 + 0]);
            float n1 = tanhf(gx[mi][2][half * 2 + 1] + r1 * gh[mi][2][half * 2 + 1]);
            float2 o;
            o.x = n0 + z0 * (hold.x - n0);
            o.y = n1 + z1 * (hold.y - n1);
            *(float2*)&g_hsnew[idx] = o;
        }
}

// ================= k3a1: q2/k2 projection (64x64, static smem, as R6) ====
#define GEMM_PROLOG() \
    const int n  = blockIdx.z; \
    const int b0 = blockIdx.x * 64; \
    const int tid = threadIdx.x, warp = tid >> 5, lane = tid & 31; \
    const int wm = warp >> 1, wn = warp & 1; \
    const int lr = lane >> 2, lc = lane & 3; \
    __shared__ float sA[2][64 * 36]; \
    __shared__ float sB[2][32 * 72]; \
    uint32_t aB = smem_u32(sA), bB = smem_u32(sB); \
    float acc[4][4] = {};

#define ISSUE_A64(kt, st, SRC, LD) \
    for (int l = tid; l < 512; l += 256) { int r = l >> 3, k4 = l & 7; \
        CPA16(aB + ((st) * 64 * 36 + r * 36 + k4 * 4) * 4, \
              &(SRC)[((b0 + r) * NBLK + n) * (LD) + (kt) * 32 + k4 * 4]); }

#define GEMM_MMA64(buf) \
    { const float* A = sA[buf]; const float* Bt = sB[buf]; \
      _Pragma("unroll") \
      for (int ks = 0; ks < 4; ks++) { \
          int k0 = ks * 8; \
          const float* ap = &A[(wm * 16 + lr) * 36 + k0 + lc]; \
          uint32_t a0 = fu(ap[0]), a1 = fu(ap[288]), a2 = fu(ap[4]), a3 = fu(ap[292]); \
          _Pragma("unroll") \
          for (int ni = 0; ni < 4; ni++) { \
              int col = wn * 32 + ni * 8 + lr; \
              uint32_t b0f = fu(Bt[(k0 + lc) * 72 + col]); \
              uint32_t b1f = fu(Bt[(k0 + lc + 4) * 72 + col]); \
              mma8(acc[ni], a0, a1, a2, a3, b0f, b1f); \
          } \
      } }

__global__ __launch_bounds__(256) void k3a1_qk(
    const float* __restrict__ Wq_, const float* __restrict__ Wk_)
{
    GEMM_PROLOG();
    #define A1_ISSUE(kt, st) { \
        ISSUE_A64(kt, st, g_hsnew, 256); \
        for (int l = tid; l < 512; l += 256) { int k = l >> 4, c4 = l & 15; \
            const float* src = (c4 < 8) ? &Wq_[(n * 256 + (kt) * 32 + k) * 32 + c4 * 4] \
                                        : &Wk_[(n * 256 + (kt) * 32 + k) * 32 + (c4 - 8) * 4]; \
            CPA16(bB + ((st) * 32 * 72 + k * 72 + c4 * 4) * 4, src); } \
        CPCOMMIT(); }
    A1_ISSUE(0, 0);
    for (int kt = 0; kt < 8; kt++) {
        if (kt < 7) { A1_ISSUE(kt + 1, (kt + 1) & 1); CPWAIT1(); }
        else CPWAIT0();
        __syncthreads();
        GEMM_MMA64(kt & 1);
        __syncthreads();
    }
    #pragma unroll
    for (int ni = 0; ni < 4; ni++) {
        int col = wn * 32 + ni * 8 + 2 * lc;
        float* dst = (col < 32) ? g_q2 : g_k2;
        int cc = col & 31;
        int r0 = b0 + wm * 16 + lr, r1 = r0 + 8;
        *(float2*)&dst[(r0 * NBLK + n) * 32 + cc] = make_float2(acc[ni][0], acc[ni][1]);
        *(float2*)&dst[(r1 * NBLK + n) * 32 + cc] = make_float2(acc[ni][2], acc[ni][3]);
    }
}

// ================= k3b: v2 = hs_new @ Wv_ (128x64, K=256) ================
__global__ __launch_bounds__(256) void k3b_v2(const float* __restrict__ Wv_)
{
    extern __shared__ float sm[];
    float* sAx = sm;             // 2 * 4608
    float* sBx = sm + 2 * 4608;  // 2 * 2304
    uint32_t aB = smem_u32(sAx), bB = smem_u32(sBx);
    const int n = blockIdx.z, b0 = blockIdx.x * 128, o0 = blockIdx.y * 64;
    const int tid = threadIdx.x, warp = tid >> 5, lane = tid & 31;
    const int wm = warp >> 1, wn = warp & 1;
    const int lr = lane >> 2, lc = lane & 3;
    float acc[2][4][4] = {};

#define K3B_ISSUE(kt, st) { \
    for (int l = tid; l < 1024; l += 256) { int r = l >> 3, k4 = l & 7; \
        CPA16(aB + ((st) * 4608 + r * 36 + k4 * 4) * 4, \
              &g_hsnew[((b0 + r) * NBLK + n) * 256 + (kt) * 32 + k4 * 4]); } \
    for (int l = tid; l < 512; l += 256) { int k = l >> 4, c4 = l & 15; \
        CPA16(bB + ((st) * 2304 + k * 72 + c4 * 4) * 4, \
              &Wv_[(n * 256 + (kt) * 32 + k) * 1024 + o0 + c4 * 4]); } \
    CPCOMMIT(); }

    K3B_ISSUE(0, 0);
    for (int kt = 0; kt < 8; kt++) {
        if (kt < 7) { K3B_ISSUE(kt + 1, (kt + 1) & 1); CPWAIT1(); }
        else CPWAIT0();
        __syncthreads();
        const float* A_ = sAx + (kt & 1) * 4608;
        const float* B_ = sBx + (kt & 1) * 2304;
        MMA_32x32(A_, B_);
        __syncthreads();
    }
    #pragma unroll
    for (int mi = 0; mi < 2; mi++)
        #pragma unroll
        for (int ni = 0; ni < 4; ni++) {
            int col = o0 + wn * 32 + ni * 8 + 2 * lc;
            int r0 = b0 + wm * 32 + mi * 16 + lr;
            *(float2*)&g_v2[(r0 * NBLK + n) * 1024 + col]       = make_float2(acc[mi][ni][0], acc[mi][ni][1]);
            *(float2*)&g_v2[((r0 + 8) * NBLK + n) * 1024 + col] = make_float2(acc[mi][ni][2], acc[mi][ni][3]);
        }
}

// ================= k3c: fused attention + ctx = att @ v2 =================
__global__ __launch_bounds__(256) void k3c_ctx()
{
    const int b = blockIdx.x;
    __shared__ float4 sV[2048];
    __shared__ float sQ[256], sK[256], sAtt[256];

    const float4* vb = (const float4*)(g_v2 + b * 8192);
    for (int l = threadIdx.x; l < 2048; l += 256) sV[l] = vb[l];
    sQ[threadIdx.x] = g_q2[b * 256 + threadIdx.x];
    sK[threadIdx.x] = g_k2[b * 256 + threadIdx.x];
    __syncthreads();

    if (threadIdx.x < 32) {
        const int lane = threadIdx.x;
        const int h = lane >> 3, nq = lane & 7;
        float sc[8], mx = -1e30f;
        #pragma unroll
        for (int m = 0; m < 8; m++) {
            float s = 0.f;
            #pragma unroll
            for (int dk = 0; dk < 8; dk++)
                s += sQ[nq * 32 + h * 8 + dk] * sK[m * 32 + h * 8 + dk];
            s *= 0.35355339059327373f;
            sc[m] = s;
            mx = fmaxf(mx, s);
        }
        float den = 0.f;
        #pragma unroll
        for (int m = 0; m < 8; m++) { sc[m] = expf(sc[m] - mx); den += sc[m]; }
        float scale = g_mask[b * NBLK + nq] / den;
        #pragma unroll
        for (int m = 0; m < 8; m++)
            sAtt[(h * 8 + nq) * 8 + m] = sc[m] * scale;
    }
    __syncthreads();

    float4* cb = (float4*)(g_ctx + b * 8192);
    for (int l = threadIdx.x; l < 2048; l += 256) {
        int nq = l >> 8, c4 = l & 255, g = c4 >> 6;
        const float* ap = &sAtt[(g * 8 + nq) * 8];
        float4 acc = make_float4(0.f, 0.f, 0.f, 0.f);
        #pragma unroll
        for (int m = 0; m < 8; m++) {
            float a = ap[m];
            float4 v = sV[m * 256 + c4];
            acc.x += a * v.x; acc.y += a * v.y; acc.z += a * v.z; acc.w += a * v.w;
        }
        cb[l] = acc;
    }
}

// ================= k3d: out = mask*(ctx@Wout + hs_new) + (1-m)*hs ========
__global__ __launch_bounds__(256) void k3d_out(
    const float* __restrict__ Wout, const float* __restrict__ hs,
    float* __restrict__ out)
{
    extern __shared__ float sm[];
    float* sAx = sm;
    float* sBx = sm + 2 * 4608;
    uint32_t aB = smem_u32(sAx), bB = smem_u32(sBx);
    const int n = blockIdx.z, b0 = blockIdx.x * 128, o0 = blockIdx.y * 64;
    const int tid = threadIdx.x, warp = tid >> 5, lane = tid & 31;
    const int wm = warp >> 1, wn = warp & 1;
    const int lr = lane >> 2, lc = lane & 3;
    float acc[2][4][4] = {};

#define K3D_ISSUE(kt, st) { \
    for (int l = tid; l < 1024; l += 256) { int r = l >> 3, k4 = l & 7; \
        CPA16(aB + ((st) * 4608 + r * 36 + k4 * 4) * 4, \
              &g_ctx[((b0 + r) * NBLK + n) * 1024 + (kt) * 32 + k4 * 4]); } \
    for (int l = tid; l < 512; l += 256) { int k = l >> 4, c4 = l & 15; \
        CPA16(bB + ((st) * 2304 + k * 72 + c4 * 4) * 4, \
              &Wout[(n * 1024 + (kt) * 32 + k) * 256 + o0 + c4 * 4]); } \
    CPCOMMIT(); }

    K3D_ISSUE(0, 0);
    for (int kt = 0; kt < 32; kt++) {
        if (kt < 31) { K3D_ISSUE(kt + 1, (kt + 1) & 1); CPWAIT1(); }
        else CPWAIT0();
        __syncthreads();
        const float* A_ = sAx + (kt & 1) * 4608;
        const float* B_ = sBx + (kt & 1) * 2304;
        MMA_32x32(A_, B_);
        __syncthreads();
    }
    #pragma unroll
    for (int mi = 0; mi < 2; mi++)
        #pragma unroll
        for (int ni = 0; ni < 4; ni++) {
            int col = o0 + wn * 32 + ni * 8 + 2 * lc;
            #pragma unroll
            for (int half = 0; half < 2; half++) {
                int row = b0 + wm * 32 + mi * 16 + lr + half * 8;
                float m = g_mask[row * NBLK + n];
                int idx = (row * NBLK + n) * HDIM + col;
                float2 hn = *(const float2*)&g_hsnew[idx];
                float2 ho = *(const float2*)&hs[idx];
                float2 r;
                r.x = m * (acc[mi][ni][half * 2]     + hn.x) + (1.f - m) * ho.x;
                r.y = m * (acc[mi][ni][half * 2 + 1] + hn.y) + (1.f - m) * ho.y;
                *(float2*)&out[idx] = r;
            }
        }
}

// =========================== launch ======================================
extern "C" void kernel_launch(void* const* d_in, const int* in_sizes, int n_in,
                              void* d_out, int out_size)
{
    const float* x1   = (const float*)d_in[0];
    const float* x2   = (const float*)d_in[1];
    const float* hs   = (const float*)d_in[2];
    const float* Wkey = (const float*)d_in[3];
    const float* bkey = (const float*)d_in[4];
    const float* Wval = (const float*)d_in[5];
    const float* bval = (const float*)d_in[6];
    const float* Wq   = (const float*)d_in[7];
    const float* Wq_  = (const float*)d_in[8];
    const float* Wk_  = (const float*)d_in[9];
    const float* Wv_  = (const float*)d_in[10];
    const float* Wout = (const float*)d_in[11];
    const float* Wx2h = (const float*)d_in[12];
    const float* Wh2h = (const float*)d_in[13];
    float* out = (float*)d_out;

    cudaFuncSetAttribute(k1a_kv, cudaFuncAttributeMaxDynamicSharedMemorySize, 51200);
    cudaFuncSetAttribute(k1a_ql, cudaFuncAttributeMaxDynamicSharedMemorySize, 43008);
    cudaFuncSetAttribute(k2_gru, cudaFuncAttributeMaxDynamicSharedMemorySize, 51200);
    cudaFuncSetAttribute(k3b_v2, cudaFuncAttributeMaxDynamicSharedMemorySize, 55296);
    cudaFuncSetAttribute(k3d_out, cudaFuncAttributeMaxDynamicSharedMemorySize, 55296);

    k1a_kv  <<<128, 256, 51200>>>(x1, x2, Wkey, Wval);
    k1a_ql  <<<dim3(64, 8), 256, 43008>>>(hs, Wq);
    k1b_gate<<<BSZ / 8, 256>>>(bkey, bval);
    k2_gru  <<<dim3(64, 16, NBLK), 256, 51200>>>(hs, Wx2h, Wh2h);
    k3a1_qk <<<dim3(128, 1, NBLK), 256>>>(Wq_, Wk_);
    k3b_v2  <<<dim3(64, 16, NBLK), 256, 55296>>>(Wv_);
    k3c_ctx <<<BSZ, 256>>>();
    k3d_out <<<dim3(64, 4, NBLK), 256, 55296>>>(Wout, hs, out);
}